// round 2
// baseline (speedup 1.0000x reference)
#include <cuda_runtime.h>

// Reference semantics reduce to:
//   alpha = softmax over a SIZE-1 axis == 1.0  (W and the GEMM are dead code)
//   attn_out[b] = sum_{l=0..63} X[b+l, :]
//   out[i, 0:512]   = 2*X[i]                    for i < 64
//   out[i, 0:512]   = X[i] + sum_{r=i-64..i-1} X[r]   for i >= 64
//   out[i, 512:1024] = X[i]
//
// Purely memory bound: read X (8 MB), write out (16.7 MB).

#define NROWS 4096
#define DCOLS 512
#define LENS  64
#define RSTRIP 16           // rows per strip; 4032 = 252 * 16
#define NCOPYBLK 4          // blocks handling rows 0..63 (16 rows each)

__global__ __launch_bounds__(128) void slide_sum_kernel(
    const float4* __restrict__ X4,   // X viewed as (4096, 128) float4
    float4* __restrict__ O4)         // out viewed as (4096, 256) float4
{
    const int c = threadIdx.x;               // 0..127 : float4 column
    const int blk = blockIdx.x;
    const int D4 = DCOLS / 4;                // 128
    const int OD4 = 2 * D4;                  // 256 (output row in float4)

    if (blk < NCOPYBLK) {
        // rows 0..63: H = 2X, right half = X
        const int i0 = blk * RSTRIP;
        #pragma unroll
        for (int r = 0; r < RSTRIP; ++r) {
            const int i = i0 + r;
            float4 x = X4[(size_t)i * D4 + c];
            float4 h = make_float4(2.f * x.x, 2.f * x.y, 2.f * x.z, 2.f * x.w);
            O4[(size_t)i * OD4 + c]      = h;
            O4[(size_t)i * OD4 + D4 + c] = x;
        }
        return;
    }

    // Sliding-window strip: rows [i0, i0+RSTRIP), i0 >= 64
    const int s  = blk - NCOPYBLK;           // 0..251
    const int i0 = LENS + s * RSTRIP;

    // Warm up window sum W = sum X[i0-64 .. i0-1]
    float4 w = make_float4(0.f, 0.f, 0.f, 0.f);
    const float4* base = X4 + (size_t)(i0 - LENS) * D4 + c;
    #pragma unroll
    for (int j = 0; j < LENS; ++j) {
        float4 x = base[(size_t)j * D4];
        w.x += x.x; w.y += x.y; w.z += x.z; w.w += x.w;
    }

    #pragma unroll
    for (int r = 0; r < RSTRIP; ++r) {
        const int i = i0 + r;
        float4 xi = X4[(size_t)i * D4 + c];
        float4 xm = X4[(size_t)(i - LENS) * D4 + c];
        float4 h  = make_float4(xi.x + w.x, xi.y + w.y, xi.z + w.z, xi.w + w.w);
        O4[(size_t)i * OD4 + c]      = h;
        O4[(size_t)i * OD4 + D4 + c] = xi;
        w.x += xi.x - xm.x;
        w.y += xi.y - xm.y;
        w.z += xi.z - xm.z;
        w.w += xi.w - xm.w;
    }
}

extern "C" void kernel_launch(void* const* d_in, const int* in_sizes, int n_in,
                              void* d_out, int out_size)
{
    const float4* X4 = (const float4*)d_in[0];   // X: (4096, 512) f32
    // d_in[1] (W) is dead code in the reference: softmax over a size-1 axis == 1.
    float4* O4 = (float4*)d_out;                 // out: (4096, 1024) f32

    const int nblocks = NCOPYBLK + (NROWS - LENS) / RSTRIP;  // 4 + 252 = 256
    slide_sum_kernel<<<nblocks, 128>>>(X4, O4);
}